// round 4
// baseline (speedup 1.0000x reference)
#include <cuda_runtime.h>
#include <math.h>

// ============================================================
// EGNN layer, N=50000, E=800000, D=128
// Round-2 fix: edge_index dtype. The harness only supports
// {float32,int32,bf16}; int64 edge_index is (almost certainly)
// delivered as int32. Reading it as long long ran 6.4MB past the
// allocation -> the illegal memory access. We now probe the layout
// on-device (int64 little-endian high words are all zero) and
// decode sender/receiver into int scratch, in-bounds either way.
//
// Structure: fused edge MLP (gather + 2x GEMM + silu + v4-red
// scatter) + node MLP (2x GEMM + silu + residual).
// GEMMs: 128x128 CTA tile, 8x8 thread tile, 256 threads.
// ============================================================

#define DD      128
#define BM      128
#define BK      32
#define APITCH  136            // 128 + 8 pad; row stride 544B (16B multiple)
#define NMAX    50000
#define EMAX    800000

__device__ __align__(16) float g_agg[(size_t)NMAX * DD];
__device__ __align__(16) float g_W1t[257 * DD];      // W1t[k][j] = W1[j][k]
__device__ __align__(16) float g_W2t[DD * DD];
__device__ __align__(16) float g_U1t[2 * DD * DD];
__device__ __align__(16) float g_U2t[DD * DD];
__device__ int g_sidx[EMAX];
__device__ int g_ridx[EMAX];
__device__ int g_is64;

struct __align__(16) TileSmem {
    float A0[BM][APITCH];   // sender h tile (later: m tile)
    float A1[BM][APITCH];   // receiver h tile (node kernel: agg tile)
    float Bs[BK][DD];
    float dist[BM];
    int   ridx[BM];
};

__device__ __forceinline__ float silu_f(float x) {
    return x * (1.0f / (1.0f + __expf(-x)));
}

__device__ __forceinline__ void red_add_v4(float* p, float a, float b, float c, float d) {
    asm volatile("red.global.add.v4.f32 [%0], {%1,%2,%3,%4};"
                 :: "l"(p), "f"(a), "f"(b), "f"(c), "f"(d) : "memory");
}

// ---- edge_index layout probe + decode ----
// int64 little-endian with values < 2^31: every odd int32 word is 0.
__global__ void detect_kernel(const int* __restrict__ ei32) {
    if (threadIdx.x == 0) {
        int any = 0;
        #pragma unroll
        for (int i = 1; i < 64; i += 2) any |= ei32[i];
        g_is64 = (any == 0) ? 1 : 0;
    }
}

__global__ void decode_kernel(const int* __restrict__ ei32, int E) {
    int e = blockIdx.x * blockDim.x + threadIdx.x;
    if (e < E) {
        if (g_is64) {                      // buffer is int64[2*E] = int32[4*E]
            g_sidx[e] = ei32[2 * e];
            g_ridx[e] = ei32[2 * E + 2 * e];
        } else {                           // buffer is int32[2*E]
            g_sidx[e] = ei32[e];
            g_ridx[e] = ei32[E + e];
        }
    }
}

__global__ void zero_agg_kernel(int n4) {
    int i = blockIdx.x * blockDim.x + threadIdx.x;
    int stride = gridDim.x * blockDim.x;
    float4* p = reinterpret_cast<float4*>(g_agg);
    float4 z = make_float4(0.f, 0.f, 0.f, 0.f);
    for (int t = i; t < n4; t += stride) p[t] = z;
}

// dst[k*J + j] = src[j*K + k]
__global__ void transpose_into_kernel(const float* __restrict__ src, int which, int J, int K) {
    float* dst = (which == 0) ? g_W1t : (which == 1) ? g_W2t : (which == 2) ? g_U1t : g_U2t;
    int idx = blockIdx.x * blockDim.x + threadIdx.x;
    if (idx < J * K) {
        int k = idx / J;
        int j = idx - k * J;
        dst[idx] = src[j * K + k];
    }
}

// ---------------- shared GEMM inner loop ----------------
__device__ __forceinline__ void gemm_chunk(const float (*A)[APITCH], const float (*Bs)[DD],
                                           int ty, int tx, int kbase, float acc[8][8]) {
    #pragma unroll
    for (int k4 = 0; k4 < BK / 4; ++k4) {
        float4 a4[8];
        #pragma unroll
        for (int i = 0; i < 8; ++i)
            a4[i] = *reinterpret_cast<const float4*>(&A[ty * 8 + i][kbase + k4 * 4]);
        #pragma unroll
        for (int kk = 0; kk < 4; ++kk) {
            int k = k4 * 4 + kk;
            float4 b0 = *reinterpret_cast<const float4*>(&Bs[k][tx * 8]);
            float4 b1 = *reinterpret_cast<const float4*>(&Bs[k][tx * 8 + 4]);
            float b[8] = {b0.x, b0.y, b0.z, b0.w, b1.x, b1.y, b1.z, b1.w};
            #pragma unroll
            for (int i = 0; i < 8; ++i) {
                float a = reinterpret_cast<const float*>(&a4[i])[kk];
                #pragma unroll
                for (int j = 0; j < 8; ++j)
                    acc[i][j] = fmaf(a, b[j], acc[i][j]);
            }
        }
    }
}

__device__ __forceinline__ void load_B_chunk(float (*Bs)[DD], const float* __restrict__ Wt,
                                             int kb, int tid) {
    const float4* W4 = reinterpret_cast<const float4*>(Wt + kb * BK * DD);
    float4* B4 = reinterpret_cast<float4*>(&Bs[0][0]);
    #pragma unroll
    for (int i = 0; i < (BK * DD / 4) / 256; ++i)
        B4[tid + i * 256] = W4[tid + i * 256];
}

// ---------------- edge kernel ----------------
__global__ __launch_bounds__(256, 1)
void edge_kernel(const float* __restrict__ h, const float* __restrict__ coords,
                 const float* __restrict__ b1, const float* __restrict__ b2,
                 int N, int E) {
    extern __shared__ __align__(16) char smem_raw[];
    TileSmem& S = *reinterpret_cast<TileSmem*>(smem_raw);
    const int tid = threadIdx.x;
    const int tx = tid & 15, ty = tid >> 4;
    const int e0 = blockIdx.x * BM;

    // per-tile indices + dist (sidx parked in S.ridx slot temporarily? no:
    // keep sidx in registers of the first 128 threads via smem arrays)
    __shared__ int s_sidx[BM];
    if (tid < BM) {
        int e = e0 + tid;
        int s = 0, r = 0;
        float d = 0.f;
        if (e < E) {
            s = g_sidx[e];
            r = g_ridx[e];
            float dx = coords[3 * s]     - coords[3 * r];
            float dy = coords[3 * s + 1] - coords[3 * r + 1];
            float dz = coords[3 * s + 2] - coords[3 * r + 2];
            d = sqrtf(dx * dx + dy * dy + dz * dz);
        }
        s_sidx[tid] = s;
        S.ridx[tid] = r;
        S.dist[tid] = d;
    }
    __syncthreads();

    // stage sender / receiver h rows (gathers; h is L2-resident)
    const float4* h4 = reinterpret_cast<const float4*>(h);
    for (int t = tid; t < BM * (DD / 4); t += 256) {
        int e = t >> 5, q = t & 31;
        float4 v = h4[(size_t)s_sidx[e] * (DD / 4) + q];
        float4 w = h4[(size_t)S.ridx[e] * (DD / 4) + q];
        *reinterpret_cast<float4*>(&S.A0[e][q * 4]) = v;
        *reinterpret_cast<float4*>(&S.A1[e][q * 4]) = w;
    }
    __syncthreads();

    float acc[8][8];
    #pragma unroll
    for (int i = 0; i < 8; ++i)
        #pragma unroll
        for (int j = 0; j < 8; ++j) acc[i][j] = 0.f;

    // ---- layer 1: acc = h_s @ W1a^T + h_r @ W1b^T  (K = 128 each) ----
    #pragma unroll 1
    for (int part = 0; part < 2; ++part) {
        const float (*A)[APITCH] = (part == 0) ? S.A0 : S.A1;
        const float* Wt = g_W1t + part * DD * DD;
        #pragma unroll 1
        for (int kb = 0; kb < DD / BK; ++kb) {
            load_B_chunk(S.Bs, Wt, kb, tid);
            __syncthreads();
            gemm_chunk(A, S.Bs, ty, tx, kb * BK, acc);
            __syncthreads();
        }
    }

    // epilogue 1: + dist * W1[:,256] + b1, silu
    {
        float wl[8], bb[8];
        #pragma unroll
        for (int j = 0; j < 8; ++j) {
            wl[j] = g_W1t[256 * DD + tx * 8 + j];
            bb[j] = b1[tx * 8 + j];
        }
        #pragma unroll
        for (int i = 0; i < 8; ++i) {
            float d = S.dist[ty * 8 + i];
            #pragma unroll
            for (int j = 0; j < 8; ++j)
                acc[i][j] = silu_f(acc[i][j] + d * wl[j] + bb[j]);
        }
    }
    // write m tile into A0 (everyone is past the last layer-1 sync)
    #pragma unroll
    for (int i = 0; i < 8; ++i)
        #pragma unroll
        for (int j = 0; j < 8; ++j)
            S.A0[ty * 8 + i][tx * 8 + j] = acc[i][j];
    __syncthreads();

    // ---- layer 2: z = m @ W2^T ----
    #pragma unroll
    for (int i = 0; i < 8; ++i)
        #pragma unroll
        for (int j = 0; j < 8; ++j) acc[i][j] = 0.f;

    #pragma unroll 1
    for (int kb = 0; kb < DD / BK; ++kb) {
        load_B_chunk(S.Bs, g_W2t, kb, tid);
        __syncthreads();
        gemm_chunk(S.A0, S.Bs, ty, tx, kb * BK, acc);
        __syncthreads();
    }

    // epilogue 2: + b2, silu, vector-atomic scatter into agg[receiver]
    {
        float bb[8];
        #pragma unroll
        for (int j = 0; j < 8; ++j) bb[j] = b2[tx * 8 + j];
        #pragma unroll
        for (int i = 0; i < 8; ++i) {
            int er = ty * 8 + i;
            if (e0 + er < E) {
                float z[8];
                #pragma unroll
                for (int j = 0; j < 8; ++j) z[j] = silu_f(acc[i][j] + bb[j]);
                float* dst = g_agg + (size_t)S.ridx[er] * DD + tx * 8;
                red_add_v4(dst,     z[0], z[1], z[2], z[3]);
                red_add_v4(dst + 4, z[4], z[5], z[6], z[7]);
            }
        }
    }
}

// ---------------- node kernel ----------------
__global__ __launch_bounds__(256, 1)
void node_kernel(const float* __restrict__ h,
                 const float* __restrict__ c1, const float* __restrict__ c2,
                 float* __restrict__ out, int N) {
    extern __shared__ __align__(16) char smem_raw[];
    TileSmem& S = *reinterpret_cast<TileSmem*>(smem_raw);
    const int tid = threadIdx.x;
    const int tx = tid & 15, ty = tid >> 4;
    const int n0 = blockIdx.x * BM;

    const float4* h4 = reinterpret_cast<const float4*>(h);
    const float4* a4g = reinterpret_cast<const float4*>(g_agg);
    float4 zf = make_float4(0.f, 0.f, 0.f, 0.f);
    for (int t = tid; t < BM * (DD / 4); t += 256) {
        int e = t >> 5, q = t & 31;
        int n = n0 + e;
        float4 v = (n < N) ? h4[(size_t)n * (DD / 4) + q] : zf;
        float4 w = (n < N) ? a4g[(size_t)n * (DD / 4) + q] : zf;
        *reinterpret_cast<float4*>(&S.A0[e][q * 4]) = v;
        *reinterpret_cast<float4*>(&S.A1[e][q * 4]) = w;
    }
    __syncthreads();

    float acc[8][8];
    #pragma unroll
    for (int i = 0; i < 8; ++i)
        #pragma unroll
        for (int j = 0; j < 8; ++j) acc[i][j] = 0.f;

    // ---- layer 1: h @ U1a^T + agg @ U1b^T ----
    #pragma unroll 1
    for (int part = 0; part < 2; ++part) {
        const float (*A)[APITCH] = (part == 0) ? S.A0 : S.A1;
        const float* Wt = g_U1t + part * DD * DD;
        #pragma unroll 1
        for (int kb = 0; kb < DD / BK; ++kb) {
            load_B_chunk(S.Bs, Wt, kb, tid);
            __syncthreads();
            gemm_chunk(A, S.Bs, ty, tx, kb * BK, acc);
            __syncthreads();
        }
    }

    // epilogue 1: + c1, silu, store y into A0
    {
        float bb[8];
        #pragma unroll
        for (int j = 0; j < 8; ++j) bb[j] = c1[tx * 8 + j];
        #pragma unroll
        for (int i = 0; i < 8; ++i)
            #pragma unroll
            for (int j = 0; j < 8; ++j)
                S.A0[ty * 8 + i][tx * 8 + j] = silu_f(acc[i][j] + bb[j]);
    }
    __syncthreads();

    // ---- layer 2: y @ U2^T ----
    #pragma unroll
    for (int i = 0; i < 8; ++i)
        #pragma unroll
        for (int j = 0; j < 8; ++j) acc[i][j] = 0.f;

    #pragma unroll 1
    for (int kb = 0; kb < DD / BK; ++kb) {
        load_B_chunk(S.Bs, g_U2t, kb, tid);
        __syncthreads();
        gemm_chunk(S.A0, S.Bs, ty, tx, kb * BK, acc);
        __syncthreads();
    }

    // epilogue 2: out = h + (z + c2)
    {
        float bb[8];
        #pragma unroll
        for (int j = 0; j < 8; ++j) bb[j] = c2[tx * 8 + j];
        #pragma unroll
        for (int i = 0; i < 8; ++i) {
            int n = n0 + ty * 8 + i;
            if (n < N) {
                const float* hrow = h + (size_t)n * DD + tx * 8;
                float* orow = out + (size_t)n * DD + tx * 8;
                float4 h0 = *reinterpret_cast<const float4*>(hrow);
                float4 h1 = *reinterpret_cast<const float4*>(hrow + 4);
                float4 o0, o1;
                o0.x = h0.x + acc[i][0] + bb[0];
                o0.y = h0.y + acc[i][1] + bb[1];
                o0.z = h0.z + acc[i][2] + bb[2];
                o0.w = h0.w + acc[i][3] + bb[3];
                o1.x = h1.x + acc[i][4] + bb[4];
                o1.y = h1.y + acc[i][5] + bb[5];
                o1.z = h1.z + acc[i][6] + bb[6];
                o1.w = h1.w + acc[i][7] + bb[7];
                *reinterpret_cast<float4*>(orow) = o0;
                *reinterpret_cast<float4*>(orow + 4) = o1;
            }
        }
    }
}

// ---------------- launch ----------------
extern "C" void kernel_launch(void* const* d_in, const int* in_sizes, int n_in,
                              void* d_out, int out_size) {
    const float* h      = (const float*)d_in[0];
    const float* coords = (const float*)d_in[1];
    const int*   ei32   = (const int*)d_in[2];     // int32 OR int64 bits; probed on device
    const float* W1     = (const float*)d_in[3];
    const float* b1     = (const float*)d_in[4];
    const float* W2     = (const float*)d_in[5];
    const float* b2     = (const float*)d_in[6];
    const float* U1     = (const float*)d_in[7];
    const float* c1     = (const float*)d_in[8];
    const float* U2     = (const float*)d_in[9];
    const float* c2     = (const float*)d_in[10];
    float* out = (float*)d_out;

    const int N = in_sizes[0] / DD;
    const int E = in_sizes[2] / 2;

    size_t smem = sizeof(TileSmem);
    cudaFuncSetAttribute(edge_kernel, cudaFuncAttributeMaxDynamicSharedMemorySize, (int)smem);
    cudaFuncSetAttribute(node_kernel, cudaFuncAttributeMaxDynamicSharedMemorySize, (int)smem);

    // 0) probe edge_index layout + decode into int scratch
    detect_kernel<<<1, 32>>>(ei32);
    decode_kernel<<<(E + 255) / 256, 256>>>(ei32, E);

    // 1) zero aggregation buffer
    zero_agg_kernel<<<512, 256>>>(N * DD / 4);

    // 2) transpose weights into device scratch (coalesced B reads later)
    transpose_into_kernel<<<(DD * 257 + 255) / 256, 256>>>(W1, 0, DD, 257);
    transpose_into_kernel<<<(DD * DD  + 255) / 256, 256>>>(W2, 1, DD, DD);
    transpose_into_kernel<<<(DD * 256 + 255) / 256, 256>>>(U1, 2, DD, 256);
    transpose_into_kernel<<<(DD * DD  + 255) / 256, 256>>>(U2, 3, DD, DD);

    // 3) fused edge MLP + scatter
    edge_kernel<<<(E + BM - 1) / BM, 256, smem>>>(h, coords, b1, b2, N, E);

    // 4) node MLP + residual
    node_kernel<<<(N + BM - 1) / BM, 256, smem>>>(h, c1, c2, out, N);
}

// round 7
// speedup vs baseline: 2.3463x; 2.3463x over previous
#include <cuda_runtime.h>
#include <math.h>
#include <stdint.h>

// ============================================================
// EGNN layer via mma.sync tf32 (baseline PTX, works on .target sm_103 —
// tcgen05 is suffix-gated and rejected by this harness's ptxas target).
// edge: gather h -> smem(tf32), [hs@W1a^T + hr@W1b^T] +dist*wl+b1, silu
//       -> smem -> @W2^T +b2, silu -> red.v4 scatter into agg
// node: [h@U1a^T + agg@U1b^T] +c1, silu -> @U2^T +c2 +h residual
// CTA 128x128, 8 warps (2x4), warp tile 64x32, m16n8k8 tf32 mma.
// A smem pitch 132 (frag-conflict-free), B chunks pitch 136, cp.async
// double buffer from pre-rounded chunk images in device scratch.
// ============================================================

#define DD      128
#define NMAX    50000
#define EMAX    800000
#define APITCH  132
#define BPITCH  136
#define CHUNK_F (32 * BPITCH)          // 4352 floats per 32-k chunk
#define IMG_F   (4 * CHUNK_F)          // 4 chunks per 128x128 weight
#define SMEM_BYTES (128 * APITCH * 4 + 2 * CHUNK_F * 4)   // 67584 + 34816 = 102400

__device__ __align__(16) float g_agg[(size_t)NMAX * DD];
__device__ __align__(16) float g_W1a[IMG_F];
__device__ __align__(16) float g_W1b[IMG_F];
__device__ __align__(16) float g_W2[IMG_F];
__device__ __align__(16) float g_U1a[IMG_F];
__device__ __align__(16) float g_U1b[IMG_F];
__device__ __align__(16) float g_U2[IMG_F];
__device__ __align__(16) float g_wlast[DD];
__device__ int g_sidx[EMAX];
__device__ int g_ridx[EMAX];
__device__ int g_is64;

// ---------------- helpers ----------------
__device__ __forceinline__ uint32_t smem_u32(const void* p) {
    uint32_t a;
    asm("{ .reg .u64 t; cvta.to.shared.u64 t, %1; cvt.u32.u64 %0, t; }"
        : "=r"(a) : "l"(p));
    return a;
}
__device__ __forceinline__ uint32_t f2tf32(float x) {
    uint32_t r;
    asm("cvt.rna.tf32.f32 %0, %1;" : "=r"(r) : "f"(x));
    return r;
}
__device__ __forceinline__ float silu_f(float x) {
    return x * (1.0f / (1.0f + __expf(-x)));
}
__device__ __forceinline__ void red_add_v4(float* p, float a, float b, float c, float d) {
    asm volatile("red.global.add.v4.f32 [%0], {%1,%2,%3,%4};"
                 :: "l"(p), "f"(a), "f"(b), "f"(c), "f"(d) : "memory");
}
__device__ __forceinline__ void cp_async16(void* dst_smem, const void* src) {
    uint32_t d = smem_u32(dst_smem);
    asm volatile("cp.async.cg.shared.global [%0], [%1], 16;" :: "r"(d), "l"(src) : "memory");
}
#define CP_COMMIT() asm volatile("cp.async.commit_group;" ::: "memory")
#define CP_WAIT0()  asm volatile("cp.async.wait_group 0;" ::: "memory")
#define CP_WAIT1()  asm volatile("cp.async.wait_group 1;" ::: "memory")

__device__ __forceinline__ void mma_tf32(float c[4], const uint32_t a[4], const uint32_t b[2]) {
    asm volatile("mma.sync.aligned.m16n8k8.row.col.f32.tf32.tf32.f32 "
                 "{%0,%1,%2,%3}, {%4,%5,%6,%7}, {%8,%9}, {%0,%1,%2,%3};"
                 : "+f"(c[0]), "+f"(c[1]), "+f"(c[2]), "+f"(c[3])
                 : "r"(a[0]), "r"(a[1]), "r"(a[2]), "r"(a[3]), "r"(b[0]), "r"(b[1]));
}

// ---------------- prep kernels ----------------
__global__ void detect_kernel(const int* __restrict__ ei32) {
    if (threadIdx.x == 0) {
        int any = 0;
        #pragma unroll
        for (int i = 1; i < 64; i += 2) any |= ei32[i];
        g_is64 = (any == 0) ? 1 : 0;
    }
}
__global__ void decode_kernel(const int* __restrict__ ei32, int E) {
    int e = blockIdx.x * blockDim.x + threadIdx.x;
    if (e < E) {
        if (g_is64) { g_sidx[e] = ei32[2 * e]; g_ridx[e] = ei32[2 * E + 2 * e]; }
        else        { g_sidx[e] = ei32[e];     g_ridx[e] = ei32[E + e]; }
    }
}
__global__ void zero_agg_kernel(int n4) {
    int i = blockIdx.x * blockDim.x + threadIdx.x;
    int stride = gridDim.x * blockDim.x;
    float4* p = reinterpret_cast<float4*>(g_agg);
    float4 z = make_float4(0.f, 0.f, 0.f, 0.f);
    for (int t = i; t < n4; t += stride) p[t] = z;
}
// chunked B image: img[kb][kl][n] = tf32(W[n][k_off + kb*32 + kl])
__global__ void prep_kernel(const float* __restrict__ src, int which, int K_in, int k_off) {
    float* dst = (which == 0) ? g_W1a : (which == 1) ? g_W1b :
                 (which == 2) ? g_W2  : (which == 3) ? g_U1a :
                 (which == 4) ? g_U1b : g_U2;
    int idx = blockIdx.x * blockDim.x + threadIdx.x;
    if (idx < DD * DD) {
        int n = idx >> 7, k = idx & 127;
        int kb = k >> 5, kl = k & 31;
        dst[kb * CHUNK_F + kl * BPITCH + n] =
            __uint_as_float(f2tf32(src[(size_t)n * K_in + k_off + k]));
    }
}
__global__ void prep_wlast_kernel(const float* __restrict__ W1) {
    int j = threadIdx.x;
    if (j < DD) g_wlast[j] = W1[(size_t)j * 257 + 256];
}

// ---------------- mma core ----------------
// per-chunk compute: acc += A[:, kbase:kbase+32] * Bchunk^T
__device__ __forceinline__ void mma_chunk(const uint32_t* __restrict__ As,
                                          const uint32_t* __restrict__ Bc,
                                          int kbase, int wr, int wc, int gid, int tig,
                                          float acc[4][4][4]) {
    #pragma unroll
    for (int ks = 0; ks < 4; ++ks) {
        const int kc = kbase + ks * 8 + tig;
        uint32_t af[4][4];
        #pragma unroll
        for (int mt = 0; mt < 4; ++mt) {
            int r = wr * 64 + mt * 16 + gid;
            af[mt][0] = As[r * APITCH + kc];
            af[mt][1] = As[(r + 8) * APITCH + kc];
            af[mt][2] = As[r * APITCH + kc + 4];
            af[mt][3] = As[(r + 8) * APITCH + kc + 4];
        }
        uint32_t bf[4][2];
        #pragma unroll
        for (int nt = 0; nt < 4; ++nt) {
            int n = wc * 32 + nt * 8 + gid;
            bf[nt][0] = Bc[(ks * 8 + tig) * BPITCH + n];
            bf[nt][1] = Bc[(ks * 8 + tig + 4) * BPITCH + n];
        }
        #pragma unroll
        for (int mt = 0; mt < 4; ++mt)
            #pragma unroll
            for (int nt = 0; nt < 4; ++nt)
                mma_tf32(acc[mt][nt], af[mt], bf[nt]);
    }
}

__device__ __forceinline__ void load_chunk(float* dst, const float* __restrict__ src, int tid) {
    const float4* s4 = reinterpret_cast<const float4*>(src);
    float4* d4 = reinterpret_cast<float4*>(dst);
    #pragma unroll 5
    for (int i = tid; i < CHUNK_F / 4; i += 256)
        cp_async16(d4 + i, s4 + i);
}

// full K=128 pass of one weight image, accumulating
__device__ __forceinline__ void gemm_pass(const uint32_t* __restrict__ As, float* Bs,
                                          const float* __restrict__ img, int tid,
                                          int wr, int wc, int gid, int tig,
                                          float acc[4][4][4]) {
    load_chunk(Bs, img, tid);
    CP_COMMIT();
    #pragma unroll 1
    for (int kb = 0; kb < 4; ++kb) {
        if (kb < 3) {
            load_chunk(Bs + ((kb + 1) & 1) * CHUNK_F, img + (kb + 1) * CHUNK_F, tid);
            CP_COMMIT();
            CP_WAIT1();
        } else {
            CP_WAIT0();
        }
        __syncthreads();
        mma_chunk(As, reinterpret_cast<const uint32_t*>(Bs + (kb & 1) * CHUNK_F),
                  kb * 32, wr, wc, gid, tig, acc);
        __syncthreads();
    }
}

// gather one 128-row tile into As (tf32-rounded); row = tid/2, half = tid&1
__device__ __forceinline__ void gather_tile(uint32_t* As, const float* __restrict__ base,
                                            const int* __restrict__ rows, int tid) {
    int row = tid >> 1, half = tid & 1;
    const float4* src = reinterpret_cast<const float4*>(base + (size_t)rows[row] * DD + half * 64);
    uint32_t* dstp = &As[row * APITCH + half * 64];
    #pragma unroll
    for (int i = 0; i < 16; ++i) {
        float4 v = src[i];
        uint4 u;
        u.x = f2tf32(v.x); u.y = f2tf32(v.y); u.z = f2tf32(v.z); u.w = f2tf32(v.w);
        *reinterpret_cast<uint4*>(dstp + i * 4) = u;
    }
}

// ---------------- edge kernel ----------------
__global__ __launch_bounds__(256, 2)
void edge_kernel(const float* __restrict__ h, const float* __restrict__ coords,
                 const float* __restrict__ b1, const float* __restrict__ b2,
                 int N, int E) {
    extern __shared__ __align__(16) char smem_raw[];
    uint32_t* As = reinterpret_cast<uint32_t*>(smem_raw);
    float* Asf = reinterpret_cast<float*>(smem_raw);
    float* Bs = reinterpret_cast<float*>(smem_raw + 128 * APITCH * 4);
    __shared__ int s_sidx[128];
    __shared__ int s_ridx[128];
    __shared__ float s_dist[128];

    const int tid = threadIdx.x;
    const int wid = tid >> 5, lane = tid & 31;
    const int wr = wid >> 2, wc = wid & 3;
    const int gid = lane >> 2, tig = lane & 3;
    const int e0 = blockIdx.x * 128;

    if (tid < 128) {
        int e = e0 + tid;
        int s = 0, r = 0;
        float d = 0.f;
        if (e < E) {
            s = g_sidx[e];
            r = g_ridx[e];
            float dx = coords[3 * s]     - coords[3 * r];
            float dy = coords[3 * s + 1] - coords[3 * r + 1];
            float dz = coords[3 * s + 2] - coords[3 * r + 2];
            d = sqrtf(dx * dx + dy * dy + dz * dz);
        }
        s_sidx[tid] = s;
        s_ridx[tid] = r;
        s_dist[tid] = d;
    }
    __syncthreads();

    float acc[4][4][4];
    #pragma unroll
    for (int mt = 0; mt < 4; ++mt)
        #pragma unroll
        for (int nt = 0; nt < 4; ++nt)
            #pragma unroll
            for (int q = 0; q < 4; ++q) acc[mt][nt][q] = 0.f;

    // ---- layer 1: two accumulation passes ----
    gather_tile(As, h, s_sidx, tid);
    __syncthreads();
    gemm_pass(As, Bs, g_W1a, tid, wr, wc, gid, tig, acc);
    gather_tile(As, h, s_ridx, tid);
    __syncthreads();
    gemm_pass(As, Bs, g_W1b, tid, wr, wc, gid, tig, acc);

    // ---- epilogue 1: silu(acc + dist*wlast + b1) -> As (tf32) ----
    #pragma unroll
    for (int mt = 0; mt < 4; ++mt) {
        int r0 = wr * 64 + mt * 16 + gid, r1 = r0 + 8;
        float d0 = s_dist[r0], d1 = s_dist[r1];
        #pragma unroll
        for (int nt = 0; nt < 4; ++nt) {
            int c = wc * 32 + nt * 8 + 2 * tig;
            float wl0 = g_wlast[c], wl1 = g_wlast[c + 1];
            float bb0 = b1[c], bb1 = b1[c + 1];
            As[r0 * APITCH + c]     = f2tf32(silu_f(acc[mt][nt][0] + d0 * wl0 + bb0));
            As[r0 * APITCH + c + 1] = f2tf32(silu_f(acc[mt][nt][1] + d0 * wl1 + bb1));
            As[r1 * APITCH + c]     = f2tf32(silu_f(acc[mt][nt][2] + d1 * wl0 + bb0));
            As[r1 * APITCH + c + 1] = f2tf32(silu_f(acc[mt][nt][3] + d1 * wl1 + bb1));
            acc[mt][nt][0] = acc[mt][nt][1] = acc[mt][nt][2] = acc[mt][nt][3] = 0.f;
        }
    }
    __syncthreads();

    // ---- layer 2 ----
    gemm_pass(As, Bs, g_W2, tid, wr, wc, gid, tig, acc);

    // ---- epilogue 2: silu(acc + b2) -> As, then v4 scatter ----
    #pragma unroll
    for (int mt = 0; mt < 4; ++mt) {
        int r0 = wr * 64 + mt * 16 + gid, r1 = r0 + 8;
        #pragma unroll
        for (int nt = 0; nt < 4; ++nt) {
            int c = wc * 32 + nt * 8 + 2 * tig;
            float bb0 = b2[c], bb1 = b2[c + 1];
            Asf[r0 * APITCH + c]     = silu_f(acc[mt][nt][0] + bb0);
            Asf[r0 * APITCH + c + 1] = silu_f(acc[mt][nt][1] + bb1);
            Asf[r1 * APITCH + c]     = silu_f(acc[mt][nt][2] + bb0);
            Asf[r1 * APITCH + c + 1] = silu_f(acc[mt][nt][3] + bb1);
        }
    }
    __syncthreads();
    {
        int row = tid >> 1, half = tid & 1;
        if (e0 + row < E) {
            float* dst = g_agg + (size_t)s_ridx[row] * DD + half * 64;
            const float4* src = reinterpret_cast<const float4*>(&Asf[row * APITCH + half * 64]);
            #pragma unroll
            for (int i = 0; i < 16; ++i) {
                float4 z = src[i];
                red_add_v4(dst + i * 4, z.x, z.y, z.z, z.w);
            }
        }
    }
}

// ---------------- node kernel ----------------
__global__ __launch_bounds__(256, 2)
void node_kernel(const float* __restrict__ h,
                 const float* __restrict__ c1, const float* __restrict__ c2,
                 float* __restrict__ out, int N) {
    extern __shared__ __align__(16) char smem_raw[];
    uint32_t* As = reinterpret_cast<uint32_t*>(smem_raw);
    float* Asf = reinterpret_cast<float*>(smem_raw);
    float* Bs = reinterpret_cast<float*>(smem_raw + 128 * APITCH * 4);
    __shared__ int s_rows[128];

    const int tid = threadIdx.x;
    const int wid = tid >> 5, lane = tid & 31;
    const int wr = wid >> 2, wc = wid & 3;
    const int gid = lane >> 2, tig = lane & 3;
    const int n0 = blockIdx.x * 128;

    if (tid < 128) {
        int n = n0 + tid;
        s_rows[tid] = (n < N) ? n : 0;
    }
    __syncthreads();

    float acc[4][4][4];
    #pragma unroll
    for (int mt = 0; mt < 4; ++mt)
        #pragma unroll
        for (int nt = 0; nt < 4; ++nt)
            #pragma unroll
            for (int q = 0; q < 4; ++q) acc[mt][nt][q] = 0.f;

    // ---- layer 1: h@U1a^T + agg@U1b^T ----
    gather_tile(As, h, s_rows, tid);
    __syncthreads();
    gemm_pass(As, Bs, g_U1a, tid, wr, wc, gid, tig, acc);
    gather_tile(As, g_agg, s_rows, tid);
    __syncthreads();
    gemm_pass(As, Bs, g_U1b, tid, wr, wc, gid, tig, acc);

    // ---- epilogue 1: silu(acc + c1) -> As (tf32) ----
    #pragma unroll
    for (int mt = 0; mt < 4; ++mt) {
        int r0 = wr * 64 + mt * 16 + gid, r1 = r0 + 8;
        #pragma unroll
        for (int nt = 0; nt < 4; ++nt) {
            int c = wc * 32 + nt * 8 + 2 * tig;
            float bb0 = c1[c], bb1 = c1[c + 1];
            As[r0 * APITCH + c]     = f2tf32(silu_f(acc[mt][nt][0] + bb0));
            As[r0 * APITCH + c + 1] = f2tf32(silu_f(acc[mt][nt][1] + bb1));
            As[r1 * APITCH + c]     = f2tf32(silu_f(acc[mt][nt][2] + bb0));
            As[r1 * APITCH + c + 1] = f2tf32(silu_f(acc[mt][nt][3] + bb1));
            acc[mt][nt][0] = acc[mt][nt][1] = acc[mt][nt][2] = acc[mt][nt][3] = 0.f;
        }
    }
    __syncthreads();

    // ---- layer 2 ----
    gemm_pass(As, Bs, g_U2, tid, wr, wc, gid, tig, acc);

    // ---- epilogue 2: (acc + c2) -> As, then out = h + As ----
    #pragma unroll
    for (int mt = 0; mt < 4; ++mt) {
        int r0 = wr * 64 + mt * 16 + gid, r1 = r0 + 8;
        #pragma unroll
        for (int nt = 0; nt < 4; ++nt) {
            int c = wc * 32 + nt * 8 + 2 * tig;
            float bb0 = c2[c], bb1 = c2[c + 1];
            Asf[r0 * APITCH + c]     = acc[mt][nt][0] + bb0;
            Asf[r0 * APITCH + c + 1] = acc[mt][nt][1] + bb1;
            Asf[r1 * APITCH + c]     = acc[mt][nt][2] + bb0;
            Asf[r1 * APITCH + c + 1] = acc[mt][nt][3] + bb1;
        }
    }
    __syncthreads();
    {
        int row = tid >> 1, half = tid & 1;
        int n = n0 + row;
        if (n < N) {
            const float4* hv = reinterpret_cast<const float4*>(h + (size_t)n * DD + half * 64);
            const float4* uv = reinterpret_cast<const float4*>(&Asf[row * APITCH + half * 64]);
            float4* ov = reinterpret_cast<float4*>(out + (size_t)n * DD + half * 64);
            #pragma unroll
            for (int i = 0; i < 16; ++i) {
                float4 a = hv[i], b = uv[i];
                float4 o;
                o.x = a.x + b.x; o.y = a.y + b.y; o.z = a.z + b.z; o.w = a.w + b.w;
                ov[i] = o;
            }
        }
    }
}

// ---------------- launch ----------------
extern "C" void kernel_launch(void* const* d_in, const int* in_sizes, int n_in,
                              void* d_out, int out_size) {
    const float* h      = (const float*)d_in[0];
    const float* coords = (const float*)d_in[1];
    const int*   ei32   = (const int*)d_in[2];
    const float* W1     = (const float*)d_in[3];
    const float* b1     = (const float*)d_in[4];
    const float* W2     = (const float*)d_in[5];
    const float* b2     = (const float*)d_in[6];
    const float* U1     = (const float*)d_in[7];
    const float* c1     = (const float*)d_in[8];
    const float* U2     = (const float*)d_in[9];
    const float* c2     = (const float*)d_in[10];
    float* out = (float*)d_out;

    const int N = in_sizes[0] / DD;
    const int E = in_sizes[2] / 2;

    cudaFuncSetAttribute(edge_kernel, cudaFuncAttributeMaxDynamicSharedMemorySize, SMEM_BYTES);
    cudaFuncSetAttribute(node_kernel, cudaFuncAttributeMaxDynamicSharedMemorySize, SMEM_BYTES);

    detect_kernel<<<1, 32>>>(ei32);
    decode_kernel<<<(E + 255) / 256, 256>>>(ei32, E);
    zero_agg_kernel<<<512, 256>>>(N * DD / 4);

    prep_kernel<<<64, 256>>>(W1, 0, 257, 0);
    prep_kernel<<<64, 256>>>(W1, 1, 257, 128);
    prep_kernel<<<64, 256>>>(W2, 2, 128, 0);
    prep_kernel<<<64, 256>>>(U1, 3, 256, 0);
    prep_kernel<<<64, 256>>>(U1, 4, 256, 128);
    prep_kernel<<<64, 256>>>(U2, 5, 128, 0);
    prep_wlast_kernel<<<1, 128>>>(W1);

    edge_kernel<<<(E + 127) / 128, 256, SMEM_BYTES>>>(h, coords, b1, b2, N, E);
    node_kernel<<<(N + 127) / 128, 256, SMEM_BYTES>>>(h, c1, c2, out, N);
}

// round 8
// speedup vs baseline: 3.8116x; 1.6245x over previous
#include <cuda_runtime.h>
#include <cuda_fp16.h>
#include <math.h>
#include <stdint.h>

// ============================================================
// EGNN layer via fp16 mma.sync m16n8k16 (f32 accum), baseline PTX.
// fp16 mantissa == tf32 mantissa (10 bits) -> same rel_err as the
// passing tf32 kernel, 2x tensor rate, half the mma count, and
// native ldmatrix fragment loads (vs scalar LDS for tf32).
// edge: gather h->smem fp16, [hs@W1a^T + hr@W1b^T] +dist*wl+b1, silu
//       -> smem fp16 -> @W2^T +b2, silu -> red.v2 scatter (from regs)
// node: [h@U1a^T + agg@U1b^T] +c1, silu -> @U2^T +c2 + h residual
// CTA 128x128, 8 warps (2x4), warp tile 64x32.
// A smem: 128 rows x 272B (odd 16B pitch -> LDSM conflict-free).
// B: fp16 n-major chunk images (k-chunks of 64, 144B row pitch),
// cp.async double-buffered. 70KB smem -> 2 CTAs/SM.
// ============================================================

#define DD       128
#define NMAX     50000
#define EMAX     800000
#define APITCHB  272                 // bytes per A row (128 halves + pad)
#define BPITCHB  144                 // bytes per B row (64 halves + pad)
#define BCHUNKB  (128 * BPITCHB)     // 18432 B per k-chunk
#define BCHUNKH  (BCHUNKB / 2)       // 9216 halves
#define ABYTES   (128 * APITCHB)     // 34816
#define SMEM_BYTES (ABYTES + 2 * BCHUNKB)   // 71680

__device__ __align__(16) float  g_agg[(size_t)NMAX * DD];
__device__ __align__(16) __half g_W1a[2 * BCHUNKH];
__device__ __align__(16) __half g_W1b[2 * BCHUNKH];
__device__ __align__(16) __half g_W2i[2 * BCHUNKH];
__device__ __align__(16) __half g_U1a[2 * BCHUNKH];
__device__ __align__(16) __half g_U1b[2 * BCHUNKH];
__device__ __align__(16) __half g_U2i[2 * BCHUNKH];
__device__ __align__(16) float  g_wlast[DD];
__device__ int g_sidx[EMAX];
__device__ int g_ridx[EMAX];
__device__ int g_is64;

// ---------------- helpers ----------------
__device__ __forceinline__ uint32_t smem_u32(const void* p) {
    uint32_t a;
    asm("{ .reg .u64 t; cvta.to.shared.u64 t, %1; cvt.u32.u64 %0, t; }"
        : "=r"(a) : "l"(p));
    return a;
}
__device__ __forceinline__ float silu_f(float x) {
    return x * (1.0f / (1.0f + __expf(-x)));
}
__device__ __forceinline__ void red_add_v2(float* p, float a, float b) {
    asm volatile("red.global.add.v2.f32 [%0], {%1,%2};"
                 :: "l"(p), "f"(a), "f"(b) : "memory");
}
__device__ __forceinline__ void cp_async16(void* dst_smem, const void* src) {
    uint32_t d = smem_u32(dst_smem);
    asm volatile("cp.async.cg.shared.global [%0], [%1], 16;" :: "r"(d), "l"(src) : "memory");
}
#define CP_COMMIT() asm volatile("cp.async.commit_group;" ::: "memory")
#define CP_WAIT0()  asm volatile("cp.async.wait_group 0;" ::: "memory")
#define CP_WAIT1()  asm volatile("cp.async.wait_group 1;" ::: "memory")

__device__ __forceinline__ void ldsm4(uint32_t& r0, uint32_t& r1, uint32_t& r2, uint32_t& r3,
                                      uint32_t addr) {
    asm volatile("ldmatrix.sync.aligned.m8n8.x4.shared.b16 {%0,%1,%2,%3}, [%4];"
                 : "=r"(r0), "=r"(r1), "=r"(r2), "=r"(r3) : "r"(addr));
}
__device__ __forceinline__ void mma_fp16(float c[4], const uint32_t a[4], const uint32_t b[2]) {
    asm volatile("mma.sync.aligned.m16n8k16.row.col.f32.f16.f16.f32 "
                 "{%0,%1,%2,%3}, {%4,%5,%6,%7}, {%8,%9}, {%0,%1,%2,%3};"
                 : "+f"(c[0]), "+f"(c[1]), "+f"(c[2]), "+f"(c[3])
                 : "r"(a[0]), "r"(a[1]), "r"(a[2]), "r"(a[3]), "r"(b[0]), "r"(b[1]));
}

// ---------------- prep kernels ----------------
__global__ void detect_kernel(const int* __restrict__ ei32) {
    if (threadIdx.x == 0) {
        int any = 0;
        #pragma unroll
        for (int i = 1; i < 64; i += 2) any |= ei32[i];
        g_is64 = (any == 0) ? 1 : 0;
    }
}
__global__ void decode_kernel(const int* __restrict__ ei32, int E) {
    int e = blockIdx.x * blockDim.x + threadIdx.x;
    if (e < E) {
        if (g_is64) { g_sidx[e] = ei32[2 * e]; g_ridx[e] = ei32[2 * E + 2 * e]; }
        else        { g_sidx[e] = ei32[e];     g_ridx[e] = ei32[E + e]; }
    }
}
__global__ void zero_agg_kernel(int n4) {
    int i = blockIdx.x * blockDim.x + threadIdx.x;
    int stride = gridDim.x * blockDim.x;
    float4* p = reinterpret_cast<float4*>(g_agg);
    float4 z = make_float4(0.f, 0.f, 0.f, 0.f);
    for (int t = i; t < n4; t += stride) p[t] = z;
}
// one kernel preps all 6 fp16 weight chunk-images + wlast
__global__ void prep_all_kernel(const float* __restrict__ W1, const float* __restrict__ W2,
                                const float* __restrict__ U1, const float* __restrict__ U2) {
    int which = blockIdx.y;
    if (which == 6) {
        if (blockIdx.x == 0 && threadIdx.x < DD)
            g_wlast[threadIdx.x] = W1[(size_t)threadIdx.x * 257 + 256];
        return;
    }
    const float* src; __half* dst; int K_in, k_off;
    switch (which) {
        case 0: src = W1; dst = g_W1a; K_in = 257; k_off = 0;   break;
        case 1: src = W1; dst = g_W1b; K_in = 257; k_off = 128; break;
        case 2: src = W2; dst = g_W2i; K_in = 128; k_off = 0;   break;
        case 3: src = U1; dst = g_U1a; K_in = 256; k_off = 0;   break;
        case 4: src = U1; dst = g_U1b; K_in = 256; k_off = 128; break;
        default: src = U2; dst = g_U2i; K_in = 128; k_off = 0;  break;
    }
    int idx = blockIdx.x * 256 + threadIdx.x;      // 64 blocks x 256 = 16384
    int n = idx >> 7, k = idx & 127;
    int kb = k >> 6, kl = k & 63;
    dst[kb * BCHUNKH + n * (BPITCHB / 2) + kl] =
        __float2half_rn(src[(size_t)n * K_in + k_off + k]);
}

// ---------------- core pieces ----------------
__device__ __forceinline__ void load_chunk(char* dst, const __half* __restrict__ src, int tid) {
    const float4* s4 = reinterpret_cast<const float4*>(src);
    float4* d4 = reinterpret_cast<float4*>(dst);
    #pragma unroll 5
    for (int i = tid; i < BCHUNKB / 16; i += 256)
        cp_async16(d4 + i, s4 + i);
}

// gather one 128-row tile (fp32 -> fp16) into A; row = tid/2, half = tid&1
__device__ __forceinline__ void gather_tile(char* A, const float* __restrict__ base,
                                            const int* __restrict__ rows, int tid) {
    int row = tid >> 1, half = tid & 1;
    const float4* src = reinterpret_cast<const float4*>(base + (size_t)rows[row] * DD + half * 64);
    char* dstp = A + row * APITCHB + half * 128;
    #pragma unroll
    for (int i = 0; i < 8; ++i) {
        float4 v0 = src[2 * i], v1 = src[2 * i + 1];
        __half2 h0 = __floats2half2_rn(v0.x, v0.y);
        __half2 h1 = __floats2half2_rn(v0.z, v0.w);
        __half2 h2 = __floats2half2_rn(v1.x, v1.y);
        __half2 h3 = __floats2half2_rn(v1.z, v1.w);
        uint4 u;
        u.x = *reinterpret_cast<uint32_t*>(&h0);
        u.y = *reinterpret_cast<uint32_t*>(&h1);
        u.z = *reinterpret_cast<uint32_t*>(&h2);
        u.w = *reinterpret_cast<uint32_t*>(&h3);
        *reinterpret_cast<uint4*>(dstp + i * 16) = u;
    }
}

// one 64-k chunk of mma; kbaseB = byte offset of chunk's k range in A rows
__device__ __forceinline__ void mma_chunk(uint32_t Ab, uint32_t Bb, int kbaseB,
                                          int wr, int wc, int lane, float acc[4][4][4]) {
    int arow = (lane & 7) + ((lane & 8) ? 8 : 0);
    int ak   = (lane & 16) ? 8 : 0;
    int bn   = (lane & 7) + ((lane & 16) ? 8 : 0);
    int bk   = (lane & 8) ? 8 : 0;
    uint32_t abase = Ab + (wr * 64 + arow) * APITCHB + kbaseB + ak * 2;
    uint32_t bbase = Bb + (wc * 32 + bn) * BPITCHB + bk * 2;
    #pragma unroll
    for (int ks = 0; ks < 4; ++ks) {
        uint32_t af[4][4];
        #pragma unroll
        for (int mt = 0; mt < 4; ++mt)
            ldsm4(af[mt][0], af[mt][1], af[mt][2], af[mt][3],
                  abase + mt * 16 * APITCHB + ks * 32);
        uint32_t bf[2][4];
        #pragma unroll
        for (int p = 0; p < 2; ++p)
            ldsm4(bf[p][0], bf[p][1], bf[p][2], bf[p][3],
                  bbase + p * 16 * BPITCHB + ks * 32);
        #pragma unroll
        for (int mt = 0; mt < 4; ++mt)
            #pragma unroll
            for (int p = 0; p < 2; ++p) {
                mma_fp16(acc[mt][2 * p],     af[mt], &bf[p][0]);
                mma_fp16(acc[mt][2 * p + 1], af[mt], &bf[p][2]);
            }
    }
}

// K=128 pass over one weight image (2 chunks, double-buffered)
__device__ __forceinline__ void gemm_pass(uint32_t Ab, char* B0, char* B1,
                                          const __half* __restrict__ img, int tid,
                                          int wr, int wc, int lane, float acc[4][4][4]) {
    load_chunk(B0, img, tid);           CP_COMMIT();
    load_chunk(B1, img + BCHUNKH, tid); CP_COMMIT();
    CP_WAIT1();
    __syncthreads();
    mma_chunk(Ab, smem_u32(B0), 0, wr, wc, lane, acc);
    CP_WAIT0();
    __syncthreads();
    mma_chunk(Ab, smem_u32(B1), 128, wr, wc, lane, acc);
    __syncthreads();
}

// ---------------- edge kernel ----------------
__global__ __launch_bounds__(256, 2)
void edge_kernel(const float* __restrict__ h, const float* __restrict__ coords,
                 const float* __restrict__ b1, const float* __restrict__ b2,
                 int N, int E) {
    extern __shared__ __align__(16) char smem_raw[];
    char* A  = smem_raw;
    char* B0 = smem_raw + ABYTES;
    char* B1 = B0 + BCHUNKB;
    __shared__ int s_sidx[128];
    __shared__ int s_ridx[128];
    __shared__ float s_dist[128];

    const int tid = threadIdx.x;
    const int wid = tid >> 5, lane = tid & 31;
    const int wr = wid >> 2, wc = wid & 3;
    const int gid = lane >> 2, tig = lane & 3;
    const int e0 = blockIdx.x * 128;
    const uint32_t Ab = smem_u32(A);

    if (tid < 128) {
        int e = e0 + tid;
        int s = 0, r = 0;
        float d = 0.f;
        if (e < E) {
            s = g_sidx[e];
            r = g_ridx[e];
            float dx = coords[3 * s]     - coords[3 * r];
            float dy = coords[3 * s + 1] - coords[3 * r + 1];
            float dz = coords[3 * s + 2] - coords[3 * r + 2];
            d = sqrtf(dx * dx + dy * dy + dz * dz);
        }
        s_sidx[tid] = s;
        s_ridx[tid] = r;
        s_dist[tid] = d;
    }
    __syncthreads();

    float acc[4][4][4];
    #pragma unroll
    for (int mt = 0; mt < 4; ++mt)
        #pragma unroll
        for (int nt = 0; nt < 4; ++nt)
            #pragma unroll
            for (int q = 0; q < 4; ++q) acc[mt][nt][q] = 0.f;

    // ---- layer 1: hs@W1a^T then += hr@W1b^T ----
    gather_tile(A, h, s_sidx, tid);
    __syncthreads();
    gemm_pass(Ab, B0, B1, g_W1a, tid, wr, wc, lane, acc);
    gather_tile(A, h, s_ridx, tid);
    __syncthreads();
    gemm_pass(Ab, B0, B1, g_W1b, tid, wr, wc, lane, acc);

    // ---- epilogue 1: silu(acc + dist*wlast + b1) -> A (fp16) ----
    #pragma unroll
    for (int mt = 0; mt < 4; ++mt) {
        int r0 = wr * 64 + mt * 16 + gid, r1 = r0 + 8;
        float d0 = s_dist[r0], d1 = s_dist[r1];
        #pragma unroll
        for (int nt = 0; nt < 4; ++nt) {
            int c = wc * 32 + nt * 8 + 2 * tig;
            float wl0 = g_wlast[c], wl1 = g_wlast[c + 1];
            float bb0 = b1[c], bb1 = b1[c + 1];
            __half2 m0 = __floats2half2_rn(silu_f(acc[mt][nt][0] + d0 * wl0 + bb0),
                                           silu_f(acc[mt][nt][1] + d0 * wl1 + bb1));
            __half2 m1 = __floats2half2_rn(silu_f(acc[mt][nt][2] + d1 * wl0 + bb0),
                                           silu_f(acc[mt][nt][3] + d1 * wl1 + bb1));
            *reinterpret_cast<__half2*>(A + r0 * APITCHB + c * 2) = m0;
            *reinterpret_cast<__half2*>(A + r1 * APITCHB + c * 2) = m1;
            acc[mt][nt][0] = acc[mt][nt][1] = acc[mt][nt][2] = acc[mt][nt][3] = 0.f;
        }
    }
    __syncthreads();

    // ---- layer 2: m@W2^T ----
    gemm_pass(Ab, B0, B1, g_W2i, tid, wr, wc, lane, acc);

    // ---- epilogue 2: silu(acc + b2) -> red.v2 scatter from registers ----
    #pragma unroll
    for (int mt = 0; mt < 4; ++mt) {
        int r0 = wr * 64 + mt * 16 + gid, r1 = r0 + 8;
        bool v0 = (e0 + r0 < E), v1 = (e0 + r1 < E);
        float* d0p = g_agg + (size_t)s_ridx[r0] * DD;
        float* d1p = g_agg + (size_t)s_ridx[r1] * DD;
        #pragma unroll
        for (int nt = 0; nt < 4; ++nt) {
            int c = wc * 32 + nt * 8 + 2 * tig;
            float bb0 = b2[c], bb1 = b2[c + 1];
            if (v0) red_add_v2(d0p + c, silu_f(acc[mt][nt][0] + bb0),
                                        silu_f(acc[mt][nt][1] + bb1));
            if (v1) red_add_v2(d1p + c, silu_f(acc[mt][nt][2] + bb0),
                                        silu_f(acc[mt][nt][3] + bb1));
        }
    }
}

// ---------------- node kernel ----------------
__global__ __launch_bounds__(256, 2)
void node_kernel(const float* __restrict__ h,
                 const float* __restrict__ c1, const float* __restrict__ c2,
                 float* __restrict__ out, int N) {
    extern __shared__ __align__(16) char smem_raw[];
    char* A  = smem_raw;
    char* B0 = smem_raw + ABYTES;
    char* B1 = B0 + BCHUNKB;
    __shared__ int s_rows[128];

    const int tid = threadIdx.x;
    const int wid = tid >> 5, lane = tid & 31;
    const int wr = wid >> 2, wc = wid & 3;
    const int gid = lane >> 2, tig = lane & 3;
    const int n0 = blockIdx.x * 128;
    const uint32_t Ab = smem_u32(A);

    if (tid < 128) {
        int n = n0 + tid;
        s_rows[tid] = (n < N) ? n : 0;
    }
    __syncthreads();

    float acc[4][4][4];
    #pragma unroll
    for (int mt = 0; mt < 4; ++mt)
        #pragma unroll
        for (int nt = 0; nt < 4; ++nt)
            #pragma unroll
            for (int q = 0; q < 4; ++q) acc[mt][nt][q] = 0.f;

    // ---- layer 1: h@U1a^T + agg@U1b^T ----
    gather_tile(A, h, s_rows, tid);
    __syncthreads();
    gemm_pass(Ab, B0, B1, g_U1a, tid, wr, wc, lane, acc);
    gather_tile(A, g_agg, s_rows, tid);
    __syncthreads();
    gemm_pass(Ab, B0, B1, g_U1b, tid, wr, wc, lane, acc);

    // ---- epilogue 1: silu(acc + c1) -> A (fp16) ----
    #pragma unroll
    for (int mt = 0; mt < 4; ++mt) {
        int r0 = wr * 64 + mt * 16 + gid, r1 = r0 + 8;
        #pragma unroll
        for (int nt = 0; nt < 4; ++nt) {
            int c = wc * 32 + nt * 8 + 2 * tig;
            float bb0 = c1[c], bb1 = c1[c + 1];
            __half2 m0 = __floats2half2_rn(silu_f(acc[mt][nt][0] + bb0),
                                           silu_f(acc[mt][nt][1] + bb1));
            __half2 m1 = __floats2half2_rn(silu_f(acc[mt][nt][2] + bb0),
                                           silu_f(acc[mt][nt][3] + bb1));
            *reinterpret_cast<__half2*>(A + r0 * APITCHB + c * 2) = m0;
            *reinterpret_cast<__half2*>(A + r1 * APITCHB + c * 2) = m1;
            acc[mt][nt][0] = acc[mt][nt][1] = acc[mt][nt][2] = acc[mt][nt][3] = 0.f;
        }
    }
    __syncthreads();

    // ---- layer 2: y@U2^T ----
    gemm_pass(Ab, B0, B1, g_U2i, tid, wr, wc, lane, acc);

    // ---- epilogue 2: out = h + acc + c2 (from registers) ----
    #pragma unroll
    for (int mt = 0; mt < 4; ++mt) {
        int r0 = wr * 64 + mt * 16 + gid, r1 = r0 + 8;
        int na = n0 + r0, nb = n0 + r1;
        #pragma unroll
        for (int nt = 0; nt < 4; ++nt) {
            int c = wc * 32 + nt * 8 + 2 * tig;
            float bb0 = c2[c], bb1 = c2[c + 1];
            if (na < N) {
                const float2 hv = *reinterpret_cast<const float2*>(h + (size_t)na * DD + c);
                float2 o;
                o.x = hv.x + acc[mt][nt][0] + bb0;
                o.y = hv.y + acc[mt][nt][1] + bb1;
                *reinterpret_cast<float2*>(out + (size_t)na * DD + c) = o;
            }
            if (nb < N) {
                const float2 hv = *reinterpret_cast<const float2*>(h + (size_t)nb * DD + c);
                float2 o;
                o.x = hv.x + acc[mt][nt][2] + bb0;
                o.y = hv.y + acc[mt][nt][3] + bb1;
                *reinterpret_cast<float2*>(out + (size_t)nb * DD + c) = o;
            }
        }
    }
}

// ---------------- launch ----------------
extern "C" void kernel_launch(void* const* d_in, const int* in_sizes, int n_in,
                              void* d_out, int out_size) {
    const float* h      = (const float*)d_in[0];
    const float* coords = (const float*)d_in[1];
    const int*   ei32   = (const int*)d_in[2];
    const float* W1     = (const float*)d_in[3];
    const float* b1     = (const float*)d_in[4];
    const float* W2     = (const float*)d_in[5];
    const float* b2     = (const float*)d_in[6];
    const float* U1     = (const float*)d_in[7];
    const float* c1     = (const float*)d_in[8];
    const float* U2     = (const float*)d_in[9];
    const float* c2     = (const float*)d_in[10];
    float* out = (float*)d_out;

    const int N = in_sizes[0] / DD;
    const int E = in_sizes[2] / 2;

    cudaFuncSetAttribute(edge_kernel, cudaFuncAttributeMaxDynamicSharedMemorySize, SMEM_BYTES);
    cudaFuncSetAttribute(node_kernel, cudaFuncAttributeMaxDynamicSharedMemorySize, SMEM_BYTES);

    detect_kernel<<<1, 32>>>(ei32);
    decode_kernel<<<(E + 255) / 256, 256>>>(ei32, E);
    zero_agg_kernel<<<512, 256>>>(N * DD / 4);
    prep_all_kernel<<<dim3(64, 7), 256>>>(W1, W2, U1, U2);

    edge_kernel<<<(E + 127) / 128, 256, SMEM_BYTES>>>(h, coords, b1, b2, N, E);
    node_kernel<<<(N + 127) / 128, 256, SMEM_BYTES>>>(h, c1, c2, out, N);
}

// round 9
// speedup vs baseline: 6.6333x; 1.7403x over previous
#include <cuda_runtime.h>
#include <cuda_fp16.h>
#include <math.h>
#include <stdint.h>

// ============================================================
// EGNN layer, algebraically refactored + fp16 mma.sync m16n8k16.
// Key identity: hs@W1a^T + hr@W1b^T = P[sender] + Q[receiver],
// P = h@W1a^T, Q = h@W1b^T computed ONCE per node (1.6 GFLOP each)
// instead of per edge (26.2 GFLOP each). Total 83.7 -> 35.4 GFLOP.
//   pq:   P,Q = h@W1a^T, h@W1b^T        (streamed weights)
//   edge: m = silu(P[s]+Q[r]+dist*wl+b1); silu(m@W2^T+b2) scatter
//         (persistent CTAs, W2 RESIDENT in smem, one GEMM/tile)
//   node: [h@U1a^T + agg@U1b^T]+c1 silu -> @U2^T +c2 + h
// ============================================================

#define DD       128
#define NMAX     50000
#define EMAX     800000
#define APITCHB  272                 // bytes per A row (128 halves + pad)
#define BPITCHB  144                 // bytes per B row (64 halves + pad)
#define BCHUNKB  (128 * BPITCHB)     // 18432 B per 64-k chunk
#define BCHUNKH  (BCHUNKB / 2)
#define ABYTES   (128 * APITCHB)     // 34816
#define SMEM_STREAM (ABYTES + 2 * BCHUNKB)   // 71680 (pq/node kernels)
#define SMEM_EDGE   (2 * BCHUNKB + ABYTES)   // 71680 (edge: resident W2 + A)

__device__ __align__(16) float  g_agg[(size_t)NMAX * DD];
__device__ __align__(16) __half g_P[(size_t)NMAX * DD];
__device__ __align__(16) __half g_Q[(size_t)NMAX * DD];
__device__ __align__(16) __half g_W1a[2 * BCHUNKH];
__device__ __align__(16) __half g_W1b[2 * BCHUNKH];
__device__ __align__(16) __half g_W2i[2 * BCHUNKH];
__device__ __align__(16) __half g_U1a[2 * BCHUNKH];
__device__ __align__(16) __half g_U1b[2 * BCHUNKH];
__device__ __align__(16) __half g_U2i[2 * BCHUNKH];
__device__ __align__(16) float  g_wlast[DD];
__device__ int g_sidx[EMAX];
__device__ int g_ridx[EMAX];
__device__ int g_is64;

// ---------------- helpers ----------------
__device__ __forceinline__ uint32_t smem_u32(const void* p) {
    uint32_t a;
    asm("{ .reg .u64 t; cvta.to.shared.u64 t, %1; cvt.u32.u64 %0, t; }"
        : "=r"(a) : "l"(p));
    return a;
}
__device__ __forceinline__ float silu_f(float x) {
    return __fdividef(x, 1.0f + __expf(-x));
}
__device__ __forceinline__ void red_add_v2(float* p, float a, float b) {
    asm volatile("red.global.add.v2.f32 [%0], {%1,%2};"
                 :: "l"(p), "f"(a), "f"(b) : "memory");
}
__device__ __forceinline__ void cp_async16(void* dst_smem, const void* src) {
    uint32_t d = smem_u32(dst_smem);
    asm volatile("cp.async.cg.shared.global [%0], [%1], 16;" :: "r"(d), "l"(src) : "memory");
}
#define CP_COMMIT() asm volatile("cp.async.commit_group;" ::: "memory")
#define CP_WAIT0()  asm volatile("cp.async.wait_group 0;" ::: "memory")
#define CP_WAIT1()  asm volatile("cp.async.wait_group 1;" ::: "memory")

__device__ __forceinline__ void ldsm4(uint32_t& r0, uint32_t& r1, uint32_t& r2, uint32_t& r3,
                                      uint32_t addr) {
    asm volatile("ldmatrix.sync.aligned.m8n8.x4.shared.b16 {%0,%1,%2,%3}, [%4];"
                 : "=r"(r0), "=r"(r1), "=r"(r2), "=r"(r3) : "r"(addr));
}
__device__ __forceinline__ void mma_fp16(float c[4], const uint32_t a[4], const uint32_t b[2]) {
    asm volatile("mma.sync.aligned.m16n8k16.row.col.f32.f16.f16.f32 "
                 "{%0,%1,%2,%3}, {%4,%5,%6,%7}, {%8,%9}, {%0,%1,%2,%3};"
                 : "+f"(c[0]), "+f"(c[1]), "+f"(c[2]), "+f"(c[3])
                 : "r"(a[0]), "r"(a[1]), "r"(a[2]), "r"(a[3]), "r"(b[0]), "r"(b[1]));
}

// ---------------- prep kernels ----------------
__global__ void detect_kernel(const int* __restrict__ ei32) {
    if (threadIdx.x == 0) {
        int any = 0;
        #pragma unroll
        for (int i = 1; i < 64; i += 2) any |= ei32[i];
        g_is64 = (any == 0) ? 1 : 0;
    }
}
__global__ void decode_kernel(const int* __restrict__ ei32, int E) {
    int e = blockIdx.x * blockDim.x + threadIdx.x;
    if (e < E) {
        if (g_is64) { g_sidx[e] = ei32[2 * e]; g_ridx[e] = ei32[2 * E + 2 * e]; }
        else        { g_sidx[e] = ei32[e];     g_ridx[e] = ei32[E + e]; }
    }
}
__global__ void zero_agg_kernel(int n4) {
    int i = blockIdx.x * blockDim.x + threadIdx.x;
    int stride = gridDim.x * blockDim.x;
    float4* p = reinterpret_cast<float4*>(g_agg);
    float4 z = make_float4(0.f, 0.f, 0.f, 0.f);
    for (int t = i; t < n4; t += stride) p[t] = z;
}
__global__ void prep_all_kernel(const float* __restrict__ W1, const float* __restrict__ W2,
                                const float* __restrict__ U1, const float* __restrict__ U2) {
    int which = blockIdx.y;
    if (which == 6) {
        if (blockIdx.x == 0 && threadIdx.x < DD)
            g_wlast[threadIdx.x] = W1[(size_t)threadIdx.x * 257 + 256];
        return;
    }
    const float* src; __half* dst; int K_in, k_off;
    switch (which) {
        case 0: src = W1; dst = g_W1a; K_in = 257; k_off = 0;   break;
        case 1: src = W1; dst = g_W1b; K_in = 257; k_off = 128; break;
        case 2: src = W2; dst = g_W2i; K_in = 128; k_off = 0;   break;
        case 3: src = U1; dst = g_U1a; K_in = 256; k_off = 0;   break;
        case 4: src = U1; dst = g_U1b; K_in = 256; k_off = 128; break;
        default: src = U2; dst = g_U2i; K_in = 128; k_off = 0;  break;
    }
    int idx = blockIdx.x * 256 + threadIdx.x;
    int n = idx >> 7, k = idx & 127;
    int kb = k >> 6, kl = k & 63;
    dst[kb * BCHUNKH + n * (BPITCHB / 2) + kl] =
        __float2half_rn(src[(size_t)n * K_in + k_off + k]);
}

// ---------------- core pieces ----------------
__device__ __forceinline__ void load_chunk(char* dst, const __half* __restrict__ src, int tid) {
    const float4* s4 = reinterpret_cast<const float4*>(src);
    float4* d4 = reinterpret_cast<float4*>(dst);
    #pragma unroll 5
    for (int i = tid; i < BCHUNKB / 16; i += 256)
        cp_async16(d4 + i, s4 + i);
}

// gather fp32 rows -> fp16 A tile; row index via array
__device__ __forceinline__ void gather_tile(char* A, const float* __restrict__ base,
                                            const int* __restrict__ rows, int tid) {
    int row = tid >> 1, half = tid & 1;
    const float4* src = reinterpret_cast<const float4*>(base + (size_t)rows[row] * DD + half * 64);
    char* dstp = A + row * APITCHB + half * 128;
    #pragma unroll
    for (int i = 0; i < 8; ++i) {
        float4 v0 = src[2 * i], v1 = src[2 * i + 1];
        __half2 h0 = __floats2half2_rn(v0.x, v0.y);
        __half2 h1 = __floats2half2_rn(v0.z, v0.w);
        __half2 h2 = __floats2half2_rn(v1.x, v1.y);
        __half2 h3 = __floats2half2_rn(v1.z, v1.w);
        uint4 u;
        u.x = *reinterpret_cast<uint32_t*>(&h0);
        u.y = *reinterpret_cast<uint32_t*>(&h1);
        u.z = *reinterpret_cast<uint32_t*>(&h2);
        u.w = *reinterpret_cast<uint32_t*>(&h3);
        *reinterpret_cast<uint4*>(dstp + i * 16) = u;
    }
}

__device__ __forceinline__ void mma_chunk(uint32_t Ab, uint32_t Bb, int kbaseB,
                                          int wr, int wc, int lane, float acc[4][4][4]) {
    int arow = (lane & 7) + ((lane & 8) ? 8 : 0);
    int ak   = (lane & 16) ? 8 : 0;
    int bn   = (lane & 7) + ((lane & 16) ? 8 : 0);
    int bk   = (lane & 8) ? 8 : 0;
    uint32_t abase = Ab + (wr * 64 + arow) * APITCHB + kbaseB + ak * 2;
    uint32_t bbase = Bb + (wc * 32 + bn) * BPITCHB + bk * 2;
    #pragma unroll
    for (int ks = 0; ks < 4; ++ks) {
        uint32_t af[4][4];
        #pragma unroll
        for (int mt = 0; mt < 4; ++mt)
            ldsm4(af[mt][0], af[mt][1], af[mt][2], af[mt][3],
                  abase + mt * 16 * APITCHB + ks * 32);
        uint32_t bf[2][4];
        #pragma unroll
        for (int p = 0; p < 2; ++p)
            ldsm4(bf[p][0], bf[p][1], bf[p][2], bf[p][3],
                  bbase + p * 16 * BPITCHB + ks * 32);
        #pragma unroll
        for (int mt = 0; mt < 4; ++mt)
            #pragma unroll
            for (int p = 0; p < 2; ++p) {
                mma_fp16(acc[mt][2 * p],     af[mt], &bf[p][0]);
                mma_fp16(acc[mt][2 * p + 1], af[mt], &bf[p][2]);
            }
    }
}

__device__ __forceinline__ void gemm_pass(uint32_t Ab, char* B0, char* B1,
                                          const __half* __restrict__ img, int tid,
                                          int wr, int wc, int lane, float acc[4][4][4]) {
    load_chunk(B0, img, tid);           CP_COMMIT();
    load_chunk(B1, img + BCHUNKH, tid); CP_COMMIT();
    CP_WAIT1();
    __syncthreads();
    mma_chunk(Ab, smem_u32(B0), 0, wr, wc, lane, acc);
    CP_WAIT0();
    __syncthreads();
    mma_chunk(Ab, smem_u32(B1), 128, wr, wc, lane, acc);
    __syncthreads();
}

#define ZERO_ACC(acc) do {                                   \
    _Pragma("unroll")                                        \
    for (int mt = 0; mt < 4; ++mt)                           \
        _Pragma("unroll")                                    \
        for (int nt = 0; nt < 4; ++nt)                       \
            _Pragma("unroll")                                \
            for (int q = 0; q < 4; ++q) acc[mt][nt][q] = 0.f;\
} while (0)

// ---------------- pq kernel: P = h@W1a^T, Q = h@W1b^T ----------------
__global__ __launch_bounds__(256, 2)
void pq_kernel(const float* __restrict__ h, int N) {
    extern __shared__ __align__(16) char smem_raw[];
    char* A  = smem_raw;
    char* B0 = smem_raw + ABYTES;
    char* B1 = B0 + BCHUNKB;
    __shared__ int s_rows[128];

    const int tid = threadIdx.x;
    const int wid = tid >> 5, lane = tid & 31;
    const int wr = wid >> 2, wc = wid & 3;
    const int gid = lane >> 2, tig = lane & 3;
    const int n0 = blockIdx.x * 128;
    const uint32_t Ab = smem_u32(A);

    if (tid < 128) s_rows[tid] = (n0 + tid < N) ? n0 + tid : 0;
    __syncthreads();

    gather_tile(A, h, s_rows, tid);
    __syncthreads();

    float acc[4][4][4];
    #pragma unroll 1
    for (int pass = 0; pass < 2; ++pass) {
        ZERO_ACC(acc);
        gemm_pass(Ab, B0, B1, pass ? g_W1b : g_W1a, tid, wr, wc, lane, acc);
        __half* dst = pass ? g_Q : g_P;
        #pragma unroll
        for (int mt = 0; mt < 4; ++mt) {
            int r0 = wr * 64 + mt * 16 + gid, r1 = r0 + 8;
            int na = n0 + r0, nb = n0 + r1;
            #pragma unroll
            for (int nt = 0; nt < 4; ++nt) {
                int c = wc * 32 + nt * 8 + 2 * tig;
                if (na < N)
                    *reinterpret_cast<__half2*>(dst + (size_t)na * DD + c) =
                        __floats2half2_rn(acc[mt][nt][0], acc[mt][nt][1]);
                if (nb < N)
                    *reinterpret_cast<__half2*>(dst + (size_t)nb * DD + c) =
                        __floats2half2_rn(acc[mt][nt][2], acc[mt][nt][3]);
            }
        }
    }
}

// ---------------- edge kernel (persistent, W2 resident) ----------------
__global__ __launch_bounds__(256, 2)
void edge_kernel(const float* __restrict__ coords,
                 const float* __restrict__ b1, const float* __restrict__ b2,
                 int E, int ntiles) {
    extern __shared__ __align__(16) char smem_raw[];
    char* Wsm = smem_raw;                    // 2 chunks of W2, resident
    char* A   = smem_raw + 2 * BCHUNKB;
    __shared__ int s_ridx[128];
    __shared__ float s_wl[128], s_b1[128], s_b2[128];

    const int tid = threadIdx.x;
    const int wid = tid >> 5, lane = tid & 31;
    const int wr = wid >> 2, wc = wid & 3;
    const int gid = lane >> 2, tig = lane & 3;
    const uint32_t Ab = smem_u32(A);
    const uint32_t Wb = smem_u32(Wsm);

    // stage W2 + epilogue constants once
    {
        const float4* s4 = reinterpret_cast<const float4*>(g_W2i);
        float4* d4 = reinterpret_cast<float4*>(Wsm);
        #pragma unroll 5
        for (int i = tid; i < 2 * BCHUNKB / 16; i += 256)
            cp_async16(d4 + i, s4 + i);
        CP_COMMIT();
        if (tid < 128) {
            s_wl[tid] = g_wlast[tid];
            s_b1[tid] = b1[tid];
            s_b2[tid] = b2[tid];
        }
        CP_WAIT0();
    }
    __syncthreads();

    const int row = tid >> 1, half = tid & 1;

    for (int t = blockIdx.x; t < ntiles; t += gridDim.x) {
        // ---- combine: A[row] = fp16(silu(P[s]+Q[r]+dist*wl+b1)) ----
        int e = t * 128 + row;
        bool valid = (e < E);
        int s = valid ? g_sidx[e] : 0;
        int r = valid ? g_ridx[e] : 0;
        if (half == 0) s_ridx[row] = r;
        float dx = coords[3 * s]     - coords[3 * r];
        float dy = coords[3 * s + 1] - coords[3 * r + 1];
        float dz = coords[3 * s + 2] - coords[3 * r + 2];
        float dist = sqrtf(dx * dx + dy * dy + dz * dz);

        const uint4* Pp = reinterpret_cast<const uint4*>(g_P + (size_t)s * DD + half * 64);
        const uint4* Qp = reinterpret_cast<const uint4*>(g_Q + (size_t)r * DD + half * 64);
        char* dstp = A + row * APITCHB + half * 128;
        #pragma unroll
        for (int i = 0; i < 8; ++i) {
            uint4 pu = Pp[i], qu = Qp[i];
            const __half2* ph = reinterpret_cast<const __half2*>(&pu);
            const __half2* qh = reinterpret_cast<const __half2*>(&qu);
            uint4 o;
            uint32_t* ow = reinterpret_cast<uint32_t*>(&o);
            #pragma unroll
            for (int j = 0; j < 4; ++j) {
                int c = half * 64 + i * 8 + j * 2;
                float2 pf = __half22float2(ph[j]);
                float2 qf = __half22float2(qh[j]);
                float x0 = silu_f(pf.x + qf.x + dist * s_wl[c]     + s_b1[c]);
                float x1 = silu_f(pf.y + qf.y + dist * s_wl[c + 1] + s_b1[c + 1]);
                __half2 hh = __floats2half2_rn(x0, x1);
                ow[j] = *reinterpret_cast<uint32_t*>(&hh);
            }
            *reinterpret_cast<uint4*>(dstp + i * 16) = o;
        }
        __syncthreads();

        // ---- layer 2: m@W2^T (resident weights) ----
        float acc[4][4][4];
        ZERO_ACC(acc);
        mma_chunk(Ab, Wb, 0, wr, wc, lane, acc);
        mma_chunk(Ab, Wb + BCHUNKB, 128, wr, wc, lane, acc);

        // ---- epilogue: silu(acc + b2) -> red.v2 scatter ----
        int e0 = t * 128;
        #pragma unroll
        for (int mt = 0; mt < 4; ++mt) {
            int r0 = wr * 64 + mt * 16 + gid, r1 = r0 + 8;
            bool v0 = (e0 + r0 < E), v1 = (e0 + r1 < E);
            float* d0p = g_agg + (size_t)s_ridx[r0] * DD;
            float* d1p = g_agg + (size_t)s_ridx[r1] * DD;
            #pragma unroll
            for (int nt = 0; nt < 4; ++nt) {
                int c = wc * 32 + nt * 8 + 2 * tig;
                float bb0 = s_b2[c], bb1 = s_b2[c + 1];
                if (v0) red_add_v2(d0p + c, silu_f(acc[mt][nt][0] + bb0),
                                            silu_f(acc[mt][nt][1] + bb1));
                if (v1) red_add_v2(d1p + c, silu_f(acc[mt][nt][2] + bb0),
                                            silu_f(acc[mt][nt][3] + bb1));
            }
        }
        __syncthreads();
    }
}

// ---------------- node kernel (streaming, as round 8) ----------------
__global__ __launch_bounds__(256, 2)
void node_kernel(const float* __restrict__ h,
                 const float* __restrict__ c1, const float* __restrict__ c2,
                 float* __restrict__ out, int N) {
    extern __shared__ __align__(16) char smem_raw[];
    char* A  = smem_raw;
    char* B0 = smem_raw + ABYTES;
    char* B1 = B0 + BCHUNKB;
    __shared__ int s_rows[128];

    const int tid = threadIdx.x;
    const int wid = tid >> 5, lane = tid & 31;
    const int wr = wid >> 2, wc = wid & 3;
    const int gid = lane >> 2, tig = lane & 3;
    const int n0 = blockIdx.x * 128;
    const uint32_t Ab = smem_u32(A);

    if (tid < 128) s_rows[tid] = (n0 + tid < N) ? n0 + tid : 0;
    __syncthreads();

    float acc[4][4][4];
    ZERO_ACC(acc);

    gather_tile(A, h, s_rows, tid);
    __syncthreads();
    gemm_pass(Ab, B0, B1, g_U1a, tid, wr, wc, lane, acc);
    gather_tile(A, g_agg, s_rows, tid);
    __syncthreads();
    gemm_pass(Ab, B0, B1, g_U1b, tid, wr, wc, lane, acc);

    #pragma unroll
    for (int mt = 0; mt < 4; ++mt) {
        int r0 = wr * 64 + mt * 16 + gid, r1 = r0 + 8;
        #pragma unroll
        for (int nt = 0; nt < 4; ++nt) {
            int c = wc * 32 + nt * 8 + 2 * tig;
            float bb0 = c1[c], bb1 = c1[c + 1];
            __half2 m0 = __floats2half2_rn(silu_f(acc[mt][nt][0] + bb0),
                                           silu_f(acc[mt][nt][1] + bb1));
            __half2 m1 = __floats2half2_rn(silu_f(acc[mt][nt][2] + bb0),
                                           silu_f(acc[mt][nt][3] + bb1));
            *reinterpret_cast<__half2*>(A + r0 * APITCHB + c * 2) = m0;
            *reinterpret_cast<__half2*>(A + r1 * APITCHB + c * 2) = m1;
            acc[mt][nt][0] = acc[mt][nt][1] = acc[mt][nt][2] = acc[mt][nt][3] = 0.f;
        }
    }
    __syncthreads();

    gemm_pass(Ab, B0, B1, g_U2i, tid, wr, wc, lane, acc);

    #pragma unroll
    for (int mt = 0; mt < 4; ++mt) {
        int r0 = wr * 64 + mt * 16 + gid, r1 = r0 + 8;
        int na = n0 + r0, nb = n0 + r1;
        #pragma unroll
        for (int nt = 0; nt < 4; ++nt) {
            int c = wc * 32 + nt * 8 + 2 * tig;
            float bb0 = c2[c], bb1 = c2[c + 1];
            if (na < N) {
                const float2 hv = *reinterpret_cast<const float2*>(h + (size_t)na * DD + c);
                float2 o;
                o.x = hv.x + acc[mt][nt][0] + bb0;
                o.y = hv.y + acc[mt][nt][1] + bb1;
                *reinterpret_cast<float2*>(out + (size_t)na * DD + c) = o;
            }
            if (nb < N) {
                const float2 hv = *reinterpret_cast<const float2*>(h + (size_t)nb * DD + c);
                float2 o;
                o.x = hv.x + acc[mt][nt][2] + bb0;
                o.y = hv.y + acc[mt][nt][3] + bb1;
                *reinterpret_cast<float2*>(out + (size_t)nb * DD + c) = o;
            }
        }
    }
}

// ---------------- launch ----------------
extern "C" void kernel_launch(void* const* d_in, const int* in_sizes, int n_in,
                              void* d_out, int out_size) {
    const float* h      = (const float*)d_in[0];
    const float* coords = (const float*)d_in[1];
    const int*   ei32   = (const int*)d_in[2];
    const float* W1     = (const float*)d_in[3];
    const float* b1     = (const float*)d_in[4];
    const float* W2     = (const float*)d_in[5];
    const float* b2     = (const float*)d_in[6];
    const float* U1     = (const float*)d_in[7];
    const float* c1     = (const float*)d_in[8];
    const float* U2     = (const float*)d_in[9];
    const float* c2     = (const float*)d_in[10];
    float* out = (float*)d_out;

    const int N = in_sizes[0] / DD;
    const int E = in_sizes[2] / 2;
    const int etiles = (E + 127) / 128;
    const int vtiles = (N + 127) / 128;

    cudaFuncSetAttribute(pq_kernel,   cudaFuncAttributeMaxDynamicSharedMemorySize, SMEM_STREAM);
    cudaFuncSetAttribute(edge_kernel, cudaFuncAttributeMaxDynamicSharedMemorySize, SMEM_EDGE);
    cudaFuncSetAttribute(node_kernel, cudaFuncAttributeMaxDynamicSharedMemorySize, SMEM_STREAM);

    detect_kernel<<<1, 32>>>(ei32);
    decode_kernel<<<(E + 255) / 256, 256>>>(ei32, E);
    zero_agg_kernel<<<512, 256>>>(N * DD / 4);
    prep_all_kernel<<<dim3(64, 7), 256>>>(W1, W2, U1, U2);

    pq_kernel<<<vtiles, 256, SMEM_STREAM>>>(h, N);
    edge_kernel<<<296, 256, SMEM_EDGE>>>(coords, b1, b2, E, etiles);
    node_kernel<<<vtiles, 256, SMEM_STREAM>>>(h, c1, c2, out, N);
}